// round 16
// baseline (speedup 1.0000x reference)
#include <cuda_runtime.h>
#include <cuda_fp16.h>
#include <mma.h>

using namespace nvcuda;

#define NMAX   50000
#define EMAX   800000
#define H      96
#define CIN    128
#define COUT   40
#define NLAYER 5
#define DTC    0.05f

// ---------------- device scratch (static, no allocs) ----------------
__device__ int   g_deg[NMAX];
__device__ int   g_rowptr[NMAX + 1];
__device__ int   g_cursor[NMAX];
__device__ float g_deginv[NMAX];
__device__ int   g_srcs[EMAX];            // stores src*12 (fp8 uint4 row offset)
__device__ int   g_excl[NMAX];
__device__ int   g_bsum[64];
__device__ int   g_bexcl[64];
// fp16 state ping-pong: interleaved (X,Y) half2 (row = 96 half2 = 24 uint4)
__device__ __align__(16) __half2 g_XY0[(size_t)NMAX * H];
__device__ __align__(16) __half2 g_XY1[(size_t)NMAX * H];
// e4m3 gather mirrors: (X,Y) fp8 pairs, row = 192 B = 12 uint4
__device__ __align__(16) uint4 g_F80[(size_t)NMAX * 12];
__device__ __align__(16) uint4 g_F81[(size_t)NMAX * 12];
// fp16 copies of GEMM operands
__device__ __align__(16) __half g_x16[(size_t)NMAX * CIN];
__device__ __align__(16) __half g_B16[CIN * 192];

// ---------------- f32x2 packed-FMA helpers ----------------
__device__ __forceinline__ unsigned long long pack2(float v) {
    unsigned long long r; unsigned int u = __float_as_uint(v);
    asm("mov.b64 %0, {%1, %1};" : "=l"(r) : "r"(u));
    return r;
}
__device__ __forceinline__ unsigned long long packxy(float lo, float hi) {
    unsigned long long r;
    asm("mov.b64 %0, {%1, %2};" : "=l"(r) : "f"(lo), "f"(hi));
    return r;
}
__device__ __forceinline__ void unpack2(unsigned long long v, float& a, float& b) {
    unsigned int x, y;
    asm("mov.b64 {%0, %1}, %2;" : "=r"(x), "=r"(y) : "l"(v));
    a = __uint_as_float(x); b = __uint_as_float(y);
}
__device__ __forceinline__ void ffma2(unsigned long long& d,
                                      unsigned long long a, unsigned long long b) {
    asm("fma.rn.f32x2 %0, %1, %2, %0;" : "+l"(d) : "l"(a), "l"(b));
}

// ---------------- fp8 (e4m3) helpers (R6-proven round-trip) ----------------
__device__ __forceinline__ unsigned short f32_to_e4m3x2(float lo, float hi) {
    unsigned short r;
    asm("cvt.rn.satfinite.e4m3x2.f32 %0, %1, %2;" : "=h"(r) : "f"(hi), "f"(lo));
    return r;
}
__device__ __forceinline__ unsigned short h2_to_e4m3x2(unsigned int h2v) {
    unsigned short r;
    asm("cvt.rn.satfinite.e4m3x2.f16x2 %0, %1;" : "=h"(r) : "r"(h2v));
    return r;
}
__device__ __forceinline__ __half2 e4m3x2_to_h2(unsigned int v16) {
    unsigned int r;
    unsigned short s = (unsigned short)v16;
    asm("cvt.rn.f16x2.e4m3x2 %0, %1;" : "=r"(r) : "h"(s));
    return *(__half2*)&r;
}

// ---------------- CSR build ----------------
__global__ void k_deg(const int* __restrict__ dst, int E) {
    int e = blockIdx.x * blockDim.x + threadIdx.x;
    if (e < E) atomicAdd(&g_deg[dst[e]], 1);
}

__global__ __launch_bounds__(1024) void k_scan1(int N) {
    __shared__ int wsum[32];
    int tid = threadIdx.x;
    int t = blockIdx.x * 1024 + tid;
    int d = (t < N) ? g_deg[t] : 0;
    int lane = tid & 31, wid = tid >> 5;
    int v = d;
#pragma unroll
    for (int off = 1; off < 32; off <<= 1) {
        int u = __shfl_up_sync(0xffffffffu, v, off);
        if (lane >= off) v += u;
    }
    if (lane == 31) wsum[wid] = v;
    __syncthreads();
    if (wid == 0) {
        int s = wsum[lane];
#pragma unroll
        for (int off = 1; off < 32; off <<= 1) {
            int u = __shfl_up_sync(0xffffffffu, s, off);
            if (lane >= off) s += u;
        }
        wsum[lane] = s;
    }
    __syncthreads();
    int incl = v + (wid > 0 ? wsum[wid - 1] : 0);
    if (t < N) g_excl[t] = incl - d;
    if (tid == 1023) g_bsum[blockIdx.x] = incl;
}

__global__ void k_scan2(int NB, int N) {
    int lane = threadIdx.x;   // 64 threads
    int s = (lane < NB) ? g_bsum[lane] : 0;
    int v = s;
#pragma unroll
    for (int off = 1; off < 64; off <<= 1) {
        int u = __shfl_up_sync(0xffffffffu, v, off);
        if ((lane & 31) >= off) v += u;
    }
    __shared__ int w0sum;
    if (lane == 31) w0sum = v;
    __syncthreads();
    int incl = v + ((lane >= 32) ? w0sum : 0);
    if (lane < NB) g_bexcl[lane] = incl - s;
    if (lane == NB - 1) g_rowptr[N] = incl;
}

__global__ __launch_bounds__(256) void k_scan3(int N) {
    int t = blockIdx.x * 256 + threadIdx.x;
    if (t < N) {
        int rp = g_bexcl[t >> 10] + g_excl[t];
        g_rowptr[t] = rp;
        g_cursor[t] = rp;
        int dg = g_deg[t];
        g_deginv[t] = 1.0f / (float)(dg > 1 ? dg : 1);
    }
}

__global__ void k_scatter(const int* __restrict__ src, const int* __restrict__ dst, int E) {
    int e = blockIdx.x * blockDim.x + threadIdx.x;
    if (e < E) {
        int p = atomicAdd(&g_cursor[dst[e]], 1);
        g_srcs[p] = src[e] * 12;    // fp8 row offset in uint4 units
    }
}

// ---------------- operand pre-conversion ----------------
__global__ __launch_bounds__(256) void k_x16(const float* __restrict__ x, int total8) {
    int i = blockIdx.x * 256 + threadIdx.x;
    if (i < total8) {
        const float4* p = (const float4*)x + (size_t)i * 2;
        float4 v0 = p[0], v1 = p[1];
        __half2 h0 = __floats2half2_rn(v0.x, v0.y);
        __half2 h1 = __floats2half2_rn(v0.z, v0.w);
        __half2 h2 = __floats2half2_rn(v1.x, v1.y);
        __half2 h3 = __floats2half2_rn(v1.z, v1.w);
        uint4 o;
        o.x = *(unsigned int*)&h0; o.y = *(unsigned int*)&h1;
        o.z = *(unsigned int*)&h2; o.w = *(unsigned int*)&h3;
        ((uint4*)g_x16)[i] = o;
    }
}

__global__ __launch_bounds__(256) void k_b16(const float* __restrict__ Wx,
                                             const float* __restrict__ Wy) {
    int idx = blockIdx.x * 256 + threadIdx.x;
    if (idx < CIN * 192) {
        int k = idx / 192;
        int c = idx - k * 192;
        int ch = c >> 1;
        float w = (c & 1) ? Wy[k * H + ch] : Wx[k * H + ch];
        g_B16[idx] = __float2half(w);
    }
}

// build fp8 mirror from fp16 state (once, after lift)
__global__ __launch_bounds__(256) void k_mir(const uint4* __restrict__ XY,
                                             uint4* __restrict__ F8, int total12) {
    int i = blockIdx.x * 256 + threadIdx.x;
    if (i < total12) {
        uint4 h0 = XY[(size_t)i * 2];
        uint4 h1 = XY[(size_t)i * 2 + 1];
        uint4 o;
        o.x = (unsigned int)h2_to_e4m3x2(h0.x) | ((unsigned int)h2_to_e4m3x2(h0.y) << 16);
        o.y = (unsigned int)h2_to_e4m3x2(h0.z) | ((unsigned int)h2_to_e4m3x2(h0.w) << 16);
        o.z = (unsigned int)h2_to_e4m3x2(h1.x) | ((unsigned int)h2_to_e4m3x2(h1.y) << 16);
        o.w = (unsigned int)h2_to_e4m3x2(h1.z) | ((unsigned int)h2_to_e4m3x2(h1.w) << 16);
        F8[i] = o;
    }
}

// ---------------- lift: HMMA with prebuilt fp16 operands (R15) ----------------
__global__ __launch_bounds__(256) void k_lift(
        const float* __restrict__ bx, const float* __restrict__ by, int N) {
    __shared__ __align__(16) __half a[128][40];
    __shared__ __align__(16) __half b[32][72];
    __shared__ __align__(16) float  stage[128][64];
    int tid = threadIdx.x;
    int wp = tid >> 5;
    int cb = blockIdx.y;
    int c0 = cb * 32;
    int row0 = blockIdx.x * 128;

    wmma::fragment<wmma::accumulator, 16, 16, 16, float> acc[4];
#pragma unroll
    for (int c = 0; c < 4; ++c) wmma::fill_fragment(acc[c], 0.0f);

    for (int kt = 0; kt < CIN; kt += 32) {
#pragma unroll
        for (int j = 0; j < 2; ++j) {
            int i4 = tid + j * 256;
            int r = i4 >> 2;
            int q = i4 & 3;
            uint4 v = make_uint4(0u, 0u, 0u, 0u);
            int gr = row0 + r;
            if (gr < N) v = *(const uint4*)(g_x16 + (size_t)gr * CIN + kt + q * 8);
            *(uint4*)&a[r][q * 8] = v;
        }
        {
            int k = tid >> 3;
            int q = tid & 7;
            uint4 v = *(const uint4*)(g_B16 + (size_t)(kt + k) * 192 + cb * 64 + q * 8);
            *(uint4*)&b[k][q * 8] = v;
        }
        __syncthreads();
#pragma unroll
        for (int kk = 0; kk < 32; kk += 16) {
            wmma::fragment<wmma::matrix_a, 16, 16, 16, __half, wmma::row_major> af;
            wmma::load_matrix_sync(af, &a[wp * 16][kk], 40);
#pragma unroll
            for (int c = 0; c < 4; ++c) {
                wmma::fragment<wmma::matrix_b, 16, 16, 16, __half, wmma::row_major> bf;
                wmma::load_matrix_sync(bf, &b[kk][c * 16], 72);
                wmma::mma_sync(acc[c], af, bf, acc[c]);
            }
        }
        __syncthreads();
    }
#pragma unroll
    for (int c = 0; c < 4; ++c)
        wmma::store_matrix_sync(&stage[wp * 16][c * 16], acc[c], 64, wmma::mem_row_major);
    __syncthreads();
#pragma unroll
    for (int j = 0; j < 16; ++j) {
        int idx = tid + j * 256;
        int r = idx >> 5;
        int p = idx & 31;
        int gr = row0 + r;
        if (gr < N) {
            float2 xy = *(const float2*)&stage[r][p * 2];
            float bxv = __ldg(bx + c0 + p);
            float byv = __ldg(by + c0 + p);
            __half2 h = __floats2half2_rn(tanhf(xy.x + bxv), tanhf(xy.y + byv));
            *(unsigned int*)(&g_XY0[(size_t)gr * H + c0 + p]) = *(unsigned int*)&h;
        }
    }
}

// ---------------- one LVConv layer: fp8 gather, fp16 state ----------------
// warp per dst node. Lanes 0-11 each load the FULL fp8 row slice as one
// LDG.128 (uint4 = 16 fp8 = 8 channel (X,Y) pairs) -> 6 sectors/edge (half
// of fp16's 12). HADD2 accumulate after e4m3->f16x2 CVT. Epilogue: fp32
// Euler update from fp16 state, write fp16 state + fp8 mirror.
__global__ __launch_bounds__(256) void k_layer(
        const uint4* __restrict__ XYin,     // fp16 rows of 24 uint4
        const uint4* __restrict__ F8in,     // fp8 rows of 12 uint4
        uint4* __restrict__ XYout,
        uint4* __restrict__ F8out,
        const float* __restrict__ al, const float* __restrict__ be,
        const float* __restrict__ ga, const float* __restrict__ de,
        int N) {
    int w = (blockIdx.x * blockDim.x + threadIdx.x) >> 5;
    int lane = threadIdx.x & 31;
    if (w >= N) return;
    bool act = lane < 12;
    int s0 = __ldg(&g_rowptr[w]);
    int s1 = __ldg(&g_rowptr[w + 1]);

    __half2 acc[8];
#pragma unroll
    for (int k = 0; k < 8; ++k) acc[k] = __floats2half2_rn(0.f, 0.f);

#define ACC8(v)                                              \
    do {                                                     \
        acc[0] = __hadd2(acc[0], e4m3x2_to_h2((v).x));       \
        acc[1] = __hadd2(acc[1], e4m3x2_to_h2((v).x >> 16)); \
        acc[2] = __hadd2(acc[2], e4m3x2_to_h2((v).y));       \
        acc[3] = __hadd2(acc[3], e4m3x2_to_h2((v).y >> 16)); \
        acc[4] = __hadd2(acc[4], e4m3x2_to_h2((v).z));       \
        acc[5] = __hadd2(acc[5], e4m3x2_to_h2((v).z >> 16)); \
        acc[6] = __hadd2(acc[6], e4m3x2_to_h2((v).w));       \
        acc[7] = __hadd2(acc[7], e4m3x2_to_h2((v).w >> 16)); \
    } while (0)

    int e = s0;
    for (; e + 4 <= s1; e += 4) {
        int oA = __ldg(&g_srcs[e + 0]);
        int oB = __ldg(&g_srcs[e + 1]);
        int oC = __ldg(&g_srcs[e + 2]);
        int oD = __ldg(&g_srcs[e + 3]);
        if (act) {
            uint4 vA = __ldg(F8in + oA + lane);
            uint4 vB = __ldg(F8in + oB + lane);
            uint4 vC = __ldg(F8in + oC + lane);
            uint4 vD = __ldg(F8in + oD + lane);
            ACC8(vA); ACC8(vB); ACC8(vC); ACC8(vD);
        }
    }
    for (; e < s1; ++e) {
        int o = __ldg(&g_srcs[e]);
        if (act) {
            uint4 v = __ldg(F8in + o + lane);
            ACC8(v);
        }
    }
#undef ACC8
    if (!act) return;

    float dinv = __ldg(&g_deginv[w]);
    float aggX[8], aggY[8];
#pragma unroll
    for (int k = 0; k < 8; ++k) {
        float2 a = __half22float2(acc[k]);
        aggX[k] = a.x * dinv;
        aggY[k] = a.y * dinv;
    }

    int c0 = lane * 8;                    // 8 channels per lane
    size_t srow = (size_t)w * 24 + lane * 2;
    uint4 sv0 = __ldg(XYin + srow);
    uint4 sv1 = __ldg(XYin + srow + 1);
    float2 sf[8];
    sf[0] = __half22float2(*(__half2*)&sv0.x);
    sf[1] = __half22float2(*(__half2*)&sv0.y);
    sf[2] = __half22float2(*(__half2*)&sv0.z);
    sf[3] = __half22float2(*(__half2*)&sv0.w);
    sf[4] = __half22float2(*(__half2*)&sv1.x);
    sf[5] = __half22float2(*(__half2*)&sv1.y);
    sf[6] = __half22float2(*(__half2*)&sv1.z);
    sf[7] = __half22float2(*(__half2*)&sv1.w);

    float4 al0 = *(const float4*)(al + c0), al1 = *(const float4*)(al + c0 + 4);
    float4 be0 = *(const float4*)(be + c0), be1 = *(const float4*)(be + c0 + 4);
    float4 ga0 = *(const float4*)(ga + c0), ga1 = *(const float4*)(ga + c0 + 4);
    float4 de0 = *(const float4*)(de + c0), de1 = *(const float4*)(de + c0 + 4);
    float alv[8] = {al0.x, al0.y, al0.z, al0.w, al1.x, al1.y, al1.z, al1.w};
    float bev[8] = {be0.x, be0.y, be0.z, be0.w, be1.x, be1.y, be1.z, be1.w};
    float gav[8] = {ga0.x, ga0.y, ga0.z, ga0.w, ga1.x, ga1.y, ga1.z, ga1.w};
    float dev[8] = {de0.x, de0.y, de0.z, de0.w, de1.x, de1.y, de1.z, de1.w};

    float Xn[8], Yn[8];
#pragma unroll
    for (int k = 0; k < 8; ++k) {
        Xn[k] = sf[k].x + DTC * sf[k].x * (alv[k] - bev[k] * aggY[k]);
        Yn[k] = sf[k].y + DTC * sf[k].y * (-gav[k] + dev[k] * aggX[k]);
    }

    __half2 h[8];
#pragma unroll
    for (int k = 0; k < 8; ++k) h[k] = __floats2half2_rn(Xn[k], Yn[k]);
    uint4 o0, o1;
    o0.x = *(unsigned int*)&h[0]; o0.y = *(unsigned int*)&h[1];
    o0.z = *(unsigned int*)&h[2]; o0.w = *(unsigned int*)&h[3];
    o1.x = *(unsigned int*)&h[4]; o1.y = *(unsigned int*)&h[5];
    o1.z = *(unsigned int*)&h[6]; o1.w = *(unsigned int*)&h[7];
    XYout[srow] = o0;
    XYout[srow + 1] = o1;

    uint4 f8;
    f8.x = (unsigned int)f32_to_e4m3x2(Xn[0], Yn[0])
         | ((unsigned int)f32_to_e4m3x2(Xn[1], Yn[1]) << 16);
    f8.y = (unsigned int)f32_to_e4m3x2(Xn[2], Yn[2])
         | ((unsigned int)f32_to_e4m3x2(Xn[3], Yn[3]) << 16);
    f8.z = (unsigned int)f32_to_e4m3x2(Xn[4], Yn[4])
         | ((unsigned int)f32_to_e4m3x2(Xn[5], Yn[5]) << 16);
    f8.w = (unsigned int)f32_to_e4m3x2(Xn[6], Yn[6])
         | ((unsigned int)f32_to_e4m3x2(Xn[7], Yn[7]) << 16);
    F8out[(size_t)w * 12 + lane] = f8;
}

// ---------------- readout: out = [X|Y] @ Wr + br, fp16 state, f32x2 math ----
__global__ __launch_bounds__(128) void k_readout(
        const uint4* __restrict__ XY,
        const float* __restrict__ Wr, const float* __restrict__ br,
        float* __restrict__ out, int N) {
    __shared__ float2 xs2[128][33];
    __shared__ float  wsX[32][COUT];
    __shared__ float  wsY[32][COUT];
    int tid = threadIdx.x;
    int tx = tid & 7;
    int ty = tid >> 3;
    int row0 = blockIdx.x * 128;
    unsigned long long acc2[4][5];
#pragma unroll
    for (int p = 0; p < 4; ++p)
#pragma unroll
        for (int j = 0; j < 5; ++j) acc2[p][j] = 0ull;

    for (int kt = 0; kt < H; kt += 32) {
#pragma unroll
        for (int j = 0; j < 8; ++j) {
            int u4 = tid + j * 128;
            int r = u4 >> 3;
            int q = u4 & 7;
            int gr = row0 + r;
            uint4 v = make_uint4(0u, 0u, 0u, 0u);
            if (gr < N) v = __ldg(XY + (size_t)gr * 24 + (kt >> 2) + q);
            int cc = q * 4;
            xs2[r][cc + 0] = __half22float2(*(__half2*)&v.x);
            xs2[r][cc + 1] = __half22float2(*(__half2*)&v.y);
            xs2[r][cc + 2] = __half22float2(*(__half2*)&v.z);
            xs2[r][cc + 3] = __half22float2(*(__half2*)&v.w);
        }
#pragma unroll
        for (int j = 0; j < 10; ++j) {
            int idx = tid + j * 128;
            if (idx < 32 * COUT) {
                int k = idx / COUT;
                int c = idx - k * COUT;
                wsX[k][c] = Wr[(size_t)(kt + k) * COUT + c];
                wsY[k][c] = Wr[(size_t)(H + kt + k) * COUT + c];
            }
        }
        __syncthreads();
#pragma unroll
        for (int k = 0; k < 32; ++k) {
            float2 xv[8];
#pragma unroll
            for (int i = 0; i < 8; ++i) xv[i] = xs2[ty * 8 + i][k];
            unsigned long long XA[4], YA[4];
#pragma unroll
            for (int p = 0; p < 4; ++p) {
                XA[p] = packxy(xv[2 * p].x, xv[2 * p + 1].x);
                YA[p] = packxy(xv[2 * p].y, xv[2 * p + 1].y);
            }
#pragma unroll
            for (int j = 0; j < 5; ++j) {
                unsigned long long wxj = pack2(wsX[k][tx * 5 + j]);
                unsigned long long wyj = pack2(wsY[k][tx * 5 + j]);
#pragma unroll
                for (int p = 0; p < 4; ++p) {
                    ffma2(acc2[p][j], XA[p], wxj);
                    ffma2(acc2[p][j], YA[p], wyj);
                }
            }
        }
        __syncthreads();
    }
#pragma unroll
    for (int p = 0; p < 4; ++p) {
        int gr0 = row0 + ty * 8 + 2 * p;
#pragma unroll
        for (int j = 0; j < 5; ++j) {
            float vlo, vhi;
            unpack2(acc2[p][j], vlo, vhi);
            float bb = br[tx * 5 + j];
            if (gr0 < N)     out[(size_t)gr0 * COUT + tx * 5 + j] = vlo + bb;
            if (gr0 + 1 < N) out[(size_t)(gr0 + 1) * COUT + tx * 5 + j] = vhi + bb;
        }
    }
}

// ---------------- launch ----------------
extern "C" void kernel_launch(void* const* d_in, const int* in_sizes, int n_in,
                              void* d_out, int out_size) {
    const float* x  = (const float*)d_in[0];
    const int*   ei = (const int*)d_in[1];
    const float* Wx = (const float*)d_in[2];
    const float* bx = (const float*)d_in[3];
    const float* Wy = (const float*)d_in[4];
    const float* by = (const float*)d_in[5];
    const float* al = (const float*)d_in[6];
    const float* be = (const float*)d_in[7];
    const float* ga = (const float*)d_in[8];
    const float* de = (const float*)d_in[9];
    const float* Wr = (const float*)d_in[10];
    const float* br = (const float*)d_in[11];
    float* out = (float*)d_out;

    int N = in_sizes[0] / CIN;
    int E = in_sizes[1] / 2;
    if (N > NMAX) N = NMAX;
    if (E > EMAX) E = EMAX;
    const int* srcp = ei;
    const int* dstp = ei + E;

    static cudaStream_t s2 = nullptr;
    static cudaEvent_t evF = nullptr, evB = nullptr, evJ = nullptr;
    if (s2 == nullptr) {
        cudaStreamCreateWithFlags(&s2, cudaStreamNonBlocking);
        cudaEventCreateWithFlags(&evF, cudaEventDisableTiming);
        cudaEventCreateWithFlags(&evB, cudaEventDisableTiming);
        cudaEventCreateWithFlags(&evJ, cudaEventDisableTiming);
    }

    void* degp;
    cudaGetSymbolAddress(&degp, g_deg);

    int NB = (N + 1023) >> 10;

    // fork: B16 build + CSR chain on s2; x16 + lift + mirror on main stream
    cudaEventRecord(evF, 0);
    cudaStreamWaitEvent(s2, evF, 0);

    k_b16<<<(CIN * 192 + 255) / 256, 256, 0, s2>>>(Wx, Wy);
    cudaEventRecord(evB, s2);

    cudaMemsetAsync(degp, 0, (size_t)N * sizeof(int), s2);
    k_deg<<<(E + 255) / 256, 256, 0, s2>>>(dstp, E);
    k_scan1<<<NB, 1024, 0, s2>>>(N);
    k_scan2<<<1, 64, 0, s2>>>(NB, N);
    k_scan3<<<(N + 255) / 256, 256, 0, s2>>>(N);
    k_scatter<<<(E + 255) / 256, 256, 0, s2>>>(srcp, dstp, E);
    cudaEventRecord(evJ, s2);

    k_x16<<<(N * 16 + 255) / 256, 256>>>(x, N * 16);
    cudaStreamWaitEvent(0, evB, 0);

    dim3 gl((N + 127) / 128, 3);
    k_lift<<<gl, 256>>>(bx, by, N);

    uint4* XYb[2]; uint4* F8b[2];
    cudaGetSymbolAddress((void**)&XYb[0], g_XY0);
    cudaGetSymbolAddress((void**)&XYb[1], g_XY1);
    cudaGetSymbolAddress((void**)&F8b[0], g_F80);
    cudaGetSymbolAddress((void**)&F8b[1], g_F81);

    k_mir<<<(N * 12 + 255) / 256, 256>>>(XYb[0], F8b[0], N * 12);

    // join: layers need both CSR and lifted state
    cudaStreamWaitEvent(0, evJ, 0);

    int layerBlocks = (N * 32 + 255) / 256;
    for (int l = 0; l < NLAYER; ++l) {
        k_layer<<<layerBlocks, 256>>>(XYb[l & 1], F8b[l & 1],
                                      XYb[(l + 1) & 1], F8b[(l + 1) & 1],
                                      al + l * H, be + l * H, ga + l * H, de + l * H, N);
    }
    k_readout<<<(N + 127) / 128, 128>>>(XYb[NLAYER & 1], Wr, br, out, N);
}

// round 17
// speedup vs baseline: 1.3268x; 1.3268x over previous
#include <cuda_runtime.h>
#include <cuda_fp16.h>
#include <mma.h>

using namespace nvcuda;

#define NMAX   50000
#define EMAX   800000
#define H      96
#define CIN    128
#define COUT   40
#define NLAYER 5
#define DTC    0.05f

// ---------------- device scratch (static, no allocs) ----------------
__device__ int   g_deg[NMAX];
__device__ int   g_rowptr[NMAX + 1];
__device__ int   g_cursor[NMAX];
__device__ float g_deginv[NMAX];
__device__ int   g_srcs[EMAX];            // stores src*24 (uint4 row offset)
__device__ int   g_excl[NMAX];
__device__ int   g_bsum[64];
__device__ int   g_bexcl[64];
// fp16 state ping-pong: interleaved (X,Y) half2 (row = 96 half2 = 24 uint4)
__device__ __align__(16) __half2 g_XY0[(size_t)NMAX * H];
__device__ __align__(16) __half2 g_XY1[(size_t)NMAX * H];
// fp16 copies of GEMM operands (built once per launch)
__device__ __align__(16) __half g_x16[(size_t)NMAX * CIN];
__device__ __align__(16) __half g_B16[CIN * 192];   // interleaved (Wx,Wy) cols

// ---------------- f32x2 packed-FMA helpers ----------------
__device__ __forceinline__ unsigned long long pack2(float v) {
    unsigned long long r; unsigned int u = __float_as_uint(v);
    asm("mov.b64 %0, {%1, %1};" : "=l"(r) : "r"(u));
    return r;
}
__device__ __forceinline__ unsigned long long packxy(float lo, float hi) {
    unsigned long long r;
    asm("mov.b64 %0, {%1, %2};" : "=l"(r) : "f"(lo), "f"(hi));
    return r;
}
__device__ __forceinline__ void unpack2(unsigned long long v, float& a, float& b) {
    unsigned int x, y;
    asm("mov.b64 {%0, %1}, %2;" : "=r"(x), "=r"(y) : "l"(v));
    a = __uint_as_float(x); b = __uint_as_float(y);
}
__device__ __forceinline__ void ffma2(unsigned long long& d,
                                      unsigned long long a, unsigned long long b) {
    asm("fma.rn.f32x2 %0, %1, %2, %0;" : "+l"(d) : "l"(a), "l"(b));
}

// ---------------- CSR build ----------------
__global__ void k_deg(const int* __restrict__ dst, int E) {
    int e = blockIdx.x * blockDim.x + threadIdx.x;
    if (e < E) atomicAdd(&g_deg[dst[e]], 1);
}

__global__ __launch_bounds__(1024) void k_scan1(int N) {
    __shared__ int wsum[32];
    int tid = threadIdx.x;
    int t = blockIdx.x * 1024 + tid;
    int d = (t < N) ? g_deg[t] : 0;
    int lane = tid & 31, wid = tid >> 5;
    int v = d;
#pragma unroll
    for (int off = 1; off < 32; off <<= 1) {
        int u = __shfl_up_sync(0xffffffffu, v, off);
        if (lane >= off) v += u;
    }
    if (lane == 31) wsum[wid] = v;
    __syncthreads();
    if (wid == 0) {
        int s = wsum[lane];
#pragma unroll
        for (int off = 1; off < 32; off <<= 1) {
            int u = __shfl_up_sync(0xffffffffu, s, off);
            if (lane >= off) s += u;
        }
        wsum[lane] = s;
    }
    __syncthreads();
    int incl = v + (wid > 0 ? wsum[wid - 1] : 0);
    if (t < N) g_excl[t] = incl - d;
    if (tid == 1023) g_bsum[blockIdx.x] = incl;
}

__global__ void k_scan2(int NB, int N) {
    int lane = threadIdx.x;   // 64 threads
    int s = (lane < NB) ? g_bsum[lane] : 0;
    int v = s;
#pragma unroll
    for (int off = 1; off < 64; off <<= 1) {
        int u = __shfl_up_sync(0xffffffffu, v, off);
        if ((lane & 31) >= off) v += u;
    }
    __shared__ int w0sum;
    if (lane == 31) w0sum = v;
    __syncthreads();
    int incl = v + ((lane >= 32) ? w0sum : 0);
    if (lane < NB) g_bexcl[lane] = incl - s;
    if (lane == NB - 1) g_rowptr[N] = incl;
}

__global__ __launch_bounds__(256) void k_scan3(int N) {
    int t = blockIdx.x * 256 + threadIdx.x;
    if (t < N) {
        int rp = g_bexcl[t >> 10] + g_excl[t];
        g_rowptr[t] = rp;
        g_cursor[t] = rp;
        int dg = g_deg[t];
        g_deginv[t] = 1.0f / (float)(dg > 1 ? dg : 1);
    }
}

__global__ void k_scatter(const int* __restrict__ src, const int* __restrict__ dst, int E) {
    int e = blockIdx.x * blockDim.x + threadIdx.x;
    if (e < E) {
        int p = atomicAdd(&g_cursor[dst[e]], 1);
        g_srcs[p] = src[e] * 24;    // pre-scaled uint4 row offset
    }
}

// ---------------- operand pre-conversion ----------------
__global__ __launch_bounds__(256) void k_x16(const float* __restrict__ x, int total8) {
    int i = blockIdx.x * 256 + threadIdx.x;
    if (i < total8) {
        const float4* p = (const float4*)x + (size_t)i * 2;
        float4 v0 = p[0], v1 = p[1];
        __half2 h0 = __floats2half2_rn(v0.x, v0.y);
        __half2 h1 = __floats2half2_rn(v0.z, v0.w);
        __half2 h2 = __floats2half2_rn(v1.x, v1.y);
        __half2 h3 = __floats2half2_rn(v1.z, v1.w);
        uint4 o;
        o.x = *(unsigned int*)&h0; o.y = *(unsigned int*)&h1;
        o.z = *(unsigned int*)&h2; o.w = *(unsigned int*)&h3;
        ((uint4*)g_x16)[i] = o;
    }
}

__global__ __launch_bounds__(256) void k_b16(const float* __restrict__ Wx,
                                             const float* __restrict__ Wy) {
    int idx = blockIdx.x * 256 + threadIdx.x;
    if (idx < CIN * 192) {
        int k = idx / 192;
        int c = idx - k * 192;
        int ch = c >> 1;
        float w = (c & 1) ? Wy[k * H + ch] : Wx[k * H + ch];
        g_B16[idx] = __float2half(w);
    }
}

// ---------------- lift: HMMA with prebuilt fp16 operands (R15-proven) -------
__global__ __launch_bounds__(256) void k_lift(
        const float* __restrict__ bx, const float* __restrict__ by, int N) {
    __shared__ __align__(16) __half a[128][40];
    __shared__ __align__(16) __half b[32][72];
    __shared__ __align__(16) float  stage[128][64];
    int tid = threadIdx.x;
    int wp = tid >> 5;
    int cb = blockIdx.y;
    int c0 = cb * 32;
    int row0 = blockIdx.x * 128;

    wmma::fragment<wmma::accumulator, 16, 16, 16, float> acc[4];
#pragma unroll
    for (int c = 0; c < 4; ++c) wmma::fill_fragment(acc[c], 0.0f);

    for (int kt = 0; kt < CIN; kt += 32) {
#pragma unroll
        for (int j = 0; j < 2; ++j) {
            int i4 = tid + j * 256;
            int r = i4 >> 2;
            int q = i4 & 3;
            uint4 v = make_uint4(0u, 0u, 0u, 0u);
            int gr = row0 + r;
            if (gr < N) v = *(const uint4*)(g_x16 + (size_t)gr * CIN + kt + q * 8);
            *(uint4*)&a[r][q * 8] = v;
        }
        {
            int k = tid >> 3;
            int q = tid & 7;
            uint4 v = *(const uint4*)(g_B16 + (size_t)(kt + k) * 192 + cb * 64 + q * 8);
            *(uint4*)&b[k][q * 8] = v;
        }
        __syncthreads();
#pragma unroll
        for (int kk = 0; kk < 32; kk += 16) {
            wmma::fragment<wmma::matrix_a, 16, 16, 16, __half, wmma::row_major> af;
            wmma::load_matrix_sync(af, &a[wp * 16][kk], 40);
#pragma unroll
            for (int c = 0; c < 4; ++c) {
                wmma::fragment<wmma::matrix_b, 16, 16, 16, __half, wmma::row_major> bf;
                wmma::load_matrix_sync(bf, &b[kk][c * 16], 72);
                wmma::mma_sync(acc[c], af, bf, acc[c]);
            }
        }
        __syncthreads();
    }
#pragma unroll
    for (int c = 0; c < 4; ++c)
        wmma::store_matrix_sync(&stage[wp * 16][c * 16], acc[c], 64, wmma::mem_row_major);
    __syncthreads();
#pragma unroll
    for (int j = 0; j < 16; ++j) {
        int idx = tid + j * 256;
        int r = idx >> 5;
        int p = idx & 31;
        int gr = row0 + r;
        if (gr < N) {
            float2 xy = *(const float2*)&stage[r][p * 2];
            float bxv = __ldg(bx + c0 + p);
            float byv = __ldg(by + c0 + p);
            __half2 h = __floats2half2_rn(tanhf(xy.x + bxv), tanhf(xy.y + byv));
            *(unsigned int*)(&g_XY0[(size_t)gr * H + c0 + p]) = *(unsigned int*)&h;
        }
    }
}

// ---------------- one LVConv layer (R5/R9/R15-proven form) ----------------
__global__ __launch_bounds__(256) void k_layer(
        const uint4* __restrict__ XYin,     // rows of 24 uint4
        uint4* __restrict__ XYout,
        const float* __restrict__ al, const float* __restrict__ be,
        const float* __restrict__ ga, const float* __restrict__ de,
        int N) {
    int w = (blockIdx.x * blockDim.x + threadIdx.x) >> 5;
    int lane = threadIdx.x & 31;
    if (w >= N) return;
    bool act = lane < 24;
    int s0 = __ldg(&g_rowptr[w]);
    int s1 = __ldg(&g_rowptr[w + 1]);

    __half2 acc0 = __floats2half2_rn(0.f, 0.f);
    __half2 acc1 = acc0, acc2 = acc0, acc3 = acc0;

    int e = s0;
    for (; e + 4 <= s1; e += 4) {
        int oA = __ldg(&g_srcs[e + 0]);
        int oB = __ldg(&g_srcs[e + 1]);
        int oC = __ldg(&g_srcs[e + 2]);
        int oD = __ldg(&g_srcs[e + 3]);
        if (act) {
            uint4 vA = __ldg(XYin + oA + lane);
            uint4 vB = __ldg(XYin + oB + lane);
            uint4 vC = __ldg(XYin + oC + lane);
            uint4 vD = __ldg(XYin + oD + lane);
            acc0 = __hadd2(acc0, __hadd2(__hadd2(*(__half2*)&vA.x, *(__half2*)&vB.x),
                                         __hadd2(*(__half2*)&vC.x, *(__half2*)&vD.x)));
            acc1 = __hadd2(acc1, __hadd2(__hadd2(*(__half2*)&vA.y, *(__half2*)&vB.y),
                                         __hadd2(*(__half2*)&vC.y, *(__half2*)&vD.y)));
            acc2 = __hadd2(acc2, __hadd2(__hadd2(*(__half2*)&vA.z, *(__half2*)&vB.z),
                                         __hadd2(*(__half2*)&vC.z, *(__half2*)&vD.z)));
            acc3 = __hadd2(acc3, __hadd2(__hadd2(*(__half2*)&vA.w, *(__half2*)&vB.w),
                                         __hadd2(*(__half2*)&vC.w, *(__half2*)&vD.w)));
        }
    }
    for (; e < s1; ++e) {
        int o = __ldg(&g_srcs[e]);
        if (act) {
            uint4 v = __ldg(XYin + o + lane);
            acc0 = __hadd2(acc0, *(__half2*)&v.x);
            acc1 = __hadd2(acc1, *(__half2*)&v.y);
            acc2 = __hadd2(acc2, *(__half2*)&v.z);
            acc3 = __hadd2(acc3, *(__half2*)&v.w);
        }
    }
    if (!act) return;

    float dinv = __ldg(&g_deginv[w]);
    float2 a0 = __half22float2(acc0);
    float2 a1 = __half22float2(acc1);
    float2 a2 = __half22float2(acc2);
    float2 a3 = __half22float2(acc3);
    float aggX[4] = {a0.x * dinv, a1.x * dinv, a2.x * dinv, a3.x * dinv};
    float aggY[4] = {a0.y * dinv, a1.y * dinv, a2.y * dinv, a3.y * dinv};

    int c0 = lane * 4;
    size_t rbase = (size_t)w * 24 + lane;
    uint4 sv = __ldg(XYin + rbase);
    float2 s0f = __half22float2(*(__half2*)&sv.x);
    float2 s1f = __half22float2(*(__half2*)&sv.y);
    float2 s2f = __half22float2(*(__half2*)&sv.z);
    float2 s3f = __half22float2(*(__half2*)&sv.w);

    float4 alv = *(const float4*)(al + c0);
    float4 bev = *(const float4*)(be + c0);
    float4 gav = *(const float4*)(ga + c0);
    float4 dev = *(const float4*)(de + c0);

    float Xn0 = s0f.x + DTC * s0f.x * (alv.x - bev.x * aggY[0]);
    float Yn0 = s0f.y + DTC * s0f.y * (-gav.x + dev.x * aggX[0]);
    float Xn1 = s1f.x + DTC * s1f.x * (alv.y - bev.y * aggY[1]);
    float Yn1 = s1f.y + DTC * s1f.y * (-gav.y + dev.y * aggX[1]);
    float Xn2 = s2f.x + DTC * s2f.x * (alv.z - bev.z * aggY[2]);
    float Yn2 = s2f.y + DTC * s2f.y * (-gav.z + dev.z * aggX[2]);
    float Xn3 = s3f.x + DTC * s3f.x * (alv.w - bev.w * aggY[3]);
    float Yn3 = s3f.y + DTC * s3f.y * (-gav.w + dev.w * aggX[3]);

    __half2 h0 = __floats2half2_rn(Xn0, Yn0);
    __half2 h1 = __floats2half2_rn(Xn1, Yn1);
    __half2 h2 = __floats2half2_rn(Xn2, Yn2);
    __half2 h3 = __floats2half2_rn(Xn3, Yn3);
    uint4 hv;
    hv.x = *(unsigned int*)&h0; hv.y = *(unsigned int*)&h1;
    hv.z = *(unsigned int*)&h2; hv.w = *(unsigned int*)&h3;
    XYout[rbase] = hv;
}

// ---------------- readout: out = [X|Y] @ Wr + br, fp16 state, f32x2 math ----
__global__ __launch_bounds__(128) void k_readout(
        const uint4* __restrict__ XY,
        const float* __restrict__ Wr, const float* __restrict__ br,
        float* __restrict__ out, int N) {
    __shared__ float2 xs2[128][33];
    __shared__ float  wsX[32][COUT];
    __shared__ float  wsY[32][COUT];
    int tid = threadIdx.x;
    int tx = tid & 7;
    int ty = tid >> 3;
    int row0 = blockIdx.x * 128;
    unsigned long long acc2[4][5];
#pragma unroll
    for (int p = 0; p < 4; ++p)
#pragma unroll
        for (int j = 0; j < 5; ++j) acc2[p][j] = 0ull;

    for (int kt = 0; kt < H; kt += 32) {
#pragma unroll
        for (int j = 0; j < 8; ++j) {
            int u4 = tid + j * 128;
            int r = u4 >> 3;
            int q = u4 & 7;
            int gr = row0 + r;
            uint4 v = make_uint4(0u, 0u, 0u, 0u);
            if (gr < N) v = __ldg(XY + (size_t)gr * 24 + (kt >> 2) + q);
            int cc = q * 4;
            xs2[r][cc + 0] = __half22float2(*(__half2*)&v.x);
            xs2[r][cc + 1] = __half22float2(*(__half2*)&v.y);
            xs2[r][cc + 2] = __half22float2(*(__half2*)&v.z);
            xs2[r][cc + 3] = __half22float2(*(__half2*)&v.w);
        }
#pragma unroll
        for (int j = 0; j < 10; ++j) {
            int idx = tid + j * 128;
            if (idx < 32 * COUT) {
                int k = idx / COUT;
                int c = idx - k * COUT;
                wsX[k][c] = Wr[(size_t)(kt + k) * COUT + c];
                wsY[k][c] = Wr[(size_t)(H + kt + k) * COUT + c];
            }
        }
        __syncthreads();
#pragma unroll
        for (int k = 0; k < 32; ++k) {
            float2 xv[8];
#pragma unroll
            for (int i = 0; i < 8; ++i) xv[i] = xs2[ty * 8 + i][k];
            unsigned long long XA[4], YA[4];
#pragma unroll
            for (int p = 0; p < 4; ++p) {
                XA[p] = packxy(xv[2 * p].x, xv[2 * p + 1].x);
                YA[p] = packxy(xv[2 * p].y, xv[2 * p + 1].y);
            }
#pragma unroll
            for (int j = 0; j < 5; ++j) {
                unsigned long long wxj = pack2(wsX[k][tx * 5 + j]);
                unsigned long long wyj = pack2(wsY[k][tx * 5 + j]);
#pragma unroll
                for (int p = 0; p < 4; ++p) {
                    ffma2(acc2[p][j], XA[p], wxj);
                    ffma2(acc2[p][j], YA[p], wyj);
                }
            }
        }
        __syncthreads();
    }
#pragma unroll
    for (int p = 0; p < 4; ++p) {
        int gr0 = row0 + ty * 8 + 2 * p;
#pragma unroll
        for (int j = 0; j < 5; ++j) {
            float vlo, vhi;
            unpack2(acc2[p][j], vlo, vhi);
            float bb = br[tx * 5 + j];
            if (gr0 < N)     out[(size_t)gr0 * COUT + tx * 5 + j] = vlo + bb;
            if (gr0 + 1 < N) out[(size_t)(gr0 + 1) * COUT + tx * 5 + j] = vhi + bb;
        }
    }
}

// ---------------- launch ----------------
extern "C" void kernel_launch(void* const* d_in, const int* in_sizes, int n_in,
                              void* d_out, int out_size) {
    const float* x  = (const float*)d_in[0];
    const int*   ei = (const int*)d_in[1];
    const float* Wx = (const float*)d_in[2];
    const float* bx = (const float*)d_in[3];
    const float* Wy = (const float*)d_in[4];
    const float* by = (const float*)d_in[5];
    const float* al = (const float*)d_in[6];
    const float* be = (const float*)d_in[7];
    const float* ga = (const float*)d_in[8];
    const float* de = (const float*)d_in[9];
    const float* Wr = (const float*)d_in[10];
    const float* br = (const float*)d_in[11];
    float* out = (float*)d_out;

    int N = in_sizes[0] / CIN;
    int E = in_sizes[1] / 2;
    if (N > NMAX) N = NMAX;
    if (E > EMAX) E = EMAX;
    const int* srcp = ei;
    const int* dstp = ei + E;

    static cudaStream_t s2 = nullptr;
    static cudaEvent_t evF = nullptr, evB = nullptr, evJ = nullptr;
    if (s2 == nullptr) {
        cudaStreamCreateWithFlags(&s2, cudaStreamNonBlocking);
        cudaEventCreateWithFlags(&evF, cudaEventDisableTiming);
        cudaEventCreateWithFlags(&evB, cudaEventDisableTiming);
        cudaEventCreateWithFlags(&evJ, cudaEventDisableTiming);
    }

    void* degp;
    cudaGetSymbolAddress(&degp, g_deg);

    int NB = (N + 1023) >> 10;

    // fork: B16 build + CSR chain on s2; x16 + lift on main stream
    cudaEventRecord(evF, 0);
    cudaStreamWaitEvent(s2, evF, 0);

    k_b16<<<(CIN * 192 + 255) / 256, 256, 0, s2>>>(Wx, Wy);
    cudaEventRecord(evB, s2);

    cudaMemsetAsync(degp, 0, (size_t)N * sizeof(int), s2);
    k_deg<<<(E + 255) / 256, 256, 0, s2>>>(dstp, E);
    k_scan1<<<NB, 1024, 0, s2>>>(N);
    k_scan2<<<1, 64, 0, s2>>>(NB, N);
    k_scan3<<<(N + 255) / 256, 256, 0, s2>>>(N);
    k_scatter<<<(E + 255) / 256, 256, 0, s2>>>(srcp, dstp, E);
    cudaEventRecord(evJ, s2);

    k_x16<<<(N * 16 + 255) / 256, 256>>>(x, N * 16);
    cudaStreamWaitEvent(0, evB, 0);

    dim3 gl((N + 127) / 128, 3);
    k_lift<<<gl, 256>>>(bx, by, N);

    // join: layers need both CSR and lifted state
    cudaStreamWaitEvent(0, evJ, 0);

    uint4* XYb[2];
    cudaGetSymbolAddress((void**)&XYb[0], g_XY0);
    cudaGetSymbolAddress((void**)&XYb[1], g_XY1);

    int layerBlocks = (N * 32 + 255) / 256;
    for (int l = 0; l < NLAYER; ++l) {
        k_layer<<<layerBlocks, 256>>>(XYb[l & 1], XYb[(l + 1) & 1],
                                      al + l * H, be + l * H, ga + l * H, de + l * H, N);
    }
    k_readout<<<(N + 127) / 128, 128>>>(XYb[NLAYER & 1], Wr, br, out, N);
}